// round 7
// baseline (speedup 1.0000x reference)
#include <cuda_runtime.h>
#include <cstdint>
#include <math.h>

#define NN     256
#define NCOIL  8
#define KTOT   17408
#define NVEC   512
#define KT_CTA 64
#define NCTA   (KTOT / KT_CTA)     // 272

// stage: 2 coils x 32 a-cols x 32 b
#define SA     320                 // bytes per a-col, region A (Xr/Xi pairs), 80w =16 mod 32
#define SB     160                 // bytes per a-col, region B (Xs pairs), 40w = 8 mod 32
#define ASZ    (32 * SA)
#define BSZ    (32 * SB)
#define COILB  (ASZ + BSZ)         // 15360
#define STAGEB (2 * COILB)         // 30720
#define NBUF   2
#define RINGB  (NBUF * STAGEB)     // 61440
#define SEEDB  16384               // 256 thr x 4 mm x 16B
#define EPIB   16384               // 256 thr x 4 mm x 16B
#define SREDB  3072                // 3 partials x 2 coils x 64 k x 8B
#define SMEM_BYTES (RINGB + SEEDB + EPIB + SREDB)   // 97280
#define NSTAGE 256
#define SLAB   3072

// packed Xc: [c][ach][bq][a-local(32)][96 words]  (same as prior round)
__device__ float gX[(size_t)NCOIL * 64 * SLAB];

// ------------------------- helpers -------------------------
__device__ __forceinline__ uint32_t smem_u32(const void* p) {
    uint32_t a;
    asm("{ .reg .u64 t; cvta.to.shared.u64 t, %1; cvt.u32.u64 %0, t; }"
        : "=r"(a) : "l"(p));
    return a;
}
__device__ __forceinline__ float tf32r(float x) {
    uint32_t u;
    asm("cvt.rna.tf32.f32 %0, %1;" : "=r"(u) : "f"(x));
    return __uint_as_float(u);
}
__device__ __forceinline__ void cp16(uint32_t dst, const float* src) {
    asm volatile("cp.async.cg.shared.global [%0], [%1], 16;"
                 :: "r"(dst), "l"(src) : "memory");
}
#define CP_COMMIT() asm volatile("cp.async.commit_group;" ::: "memory")
#define CP_WAIT0()  asm volatile("cp.async.wait_group 0;" ::: "memory")

__device__ __forceinline__ void lds128(uint32_t& a, uint32_t& b, uint32_t& c,
                                       uint32_t& d, uint32_t addr) {
    asm("ld.shared.v4.b32 {%0,%1,%2,%3}, [%4];"
        : "=r"(a), "=r"(b), "=r"(c), "=r"(d) : "r"(addr));
}
__device__ __forceinline__ void lds64(uint32_t& a, uint32_t& b, uint32_t addr) {
    asm("ld.shared.v2.b32 {%0,%1}, [%2];" : "=r"(a), "=r"(b) : "r"(addr));
}
__device__ __forceinline__ void lds128f(float& a, float& b, float& c, float& d,
                                        uint32_t addr) {
    asm("ld.shared.v4.f32 {%0,%1,%2,%3}, [%4];"
        : "=f"(a), "=f"(b), "=f"(c), "=f"(d) : "r"(addr));
}
__device__ __forceinline__ void sts128f(uint32_t addr, float a, float b,
                                        float c, float d) {
    asm volatile("st.shared.v4.f32 [%0], {%1,%2,%3,%4};"
                 :: "r"(addr), "f"(a), "f"(b), "f"(c), "f"(d));
}
__device__ __forceinline__ void mma8(float* d, const uint32_t* A,
                                     uint32_t b0, uint32_t b1) {
    asm volatile(
        "mma.sync.aligned.m16n8k8.row.col.f32.tf32.tf32.f32 "
        "{%0,%1,%2,%3}, {%4,%5,%6,%7}, {%8,%9}, {%0,%1,%2,%3};"
        : "+f"(d[0]), "+f"(d[1]), "+f"(d[2]), "+f"(d[3])
        : "r"(A[0]), "r"(A[1]), "r"(A[2]), "r"(A[3]), "r"(b0), "r"(b1));
}

// ------------------------- prep -------------------------
__global__ void prep_X(const float* __restrict__ input_r,
                       const float* __restrict__ C_r) {
    int idx = blockIdx.x * blockDim.x + threadIdx.x;
    if (idx >= NCOIL * NN * NN) return;
    int c = idx >> 16;
    int a = (idx >> 8) & 255;
    int b = idx & 255;
    float xr = input_r[(a * NN + b) * 2 + 0];
    float xi = input_r[(a * NN + b) * 2 + 1];
    float cr = C_r[(size_t)idx * 2 + 0];
    float ci = C_r[(size_t)idx * 2 + 1];
    float Xr = tf32r(cr * xr - ci * xi);
    float Xi = tf32r(cr * xi + ci * xr);
    float Xs = tf32r(Xr + Xi);
    int bq = b >> 5, bs = (b >> 3) & 3, q = b & 3, e = (b >> 2) & 1;
    int p = bs * 4 + q;
    size_t base = ((((size_t)c * 8 + (a >> 5)) * 8 + bq) * 32 + (a & 31)) * 96;
    gX[base + p * 4 + e]      = Xr;
    gX[base + p * 4 + 2 + e]  = Xi;
    gX[base + 64 + p * 2 + e] = Xs;
}

// ------------------------- main -------------------------
extern __shared__ char dyn_smem[];

__global__ void __launch_bounds__(256, 2)
main_kernel(const float* __restrict__ angle, const float* __restrict__ w,
            float* __restrict__ out) {
    const uint32_t S0    = smem_u32(dyn_smem);
    const uint32_t RING  = S0;
    const uint32_t SEEDS = S0 + RINGB;
    const uint32_t EPI   = SEEDS + SEEDB;
    const uint32_t SRED  = EPI + EPIB;

    const int tid  = threadIdx.x;
    const int lane = tid & 31;
    const int warp = tid >> 5;
    const int ag   = warp & 3;        // a-group (8 cols)
    const int kg   = warp >> 2;       // k-group (32 rows)
    const int r    = lane >> 2;
    const int q    = lane & 3;
    const int kblk = blockIdx.x * KT_CTA;
    const int co0  = ag * 8 + 2 * q;

    // ---- per-thread constants: 4 k-rows (mm), seeds + epi consts to smem ----
    float stp_r[4], stp_i[4], s_mm[4];
    const float SC = 1.00024414f;
#pragma unroll
    for (int mm = 0; mm < 4; ++mm) {
        int kk = kblk + kg * 32 + mm * 8 + r;
        float t = angle[2 * kk + 1];
        float sr, cr;
        sincosf(t * (float)(q - 128), &sr, &cr);
        float s0r = cr * SC, s0i = sr * SC;
        sincosf(t * (float)(q - 124), &sr, &cr);
        sts128f(SEEDS + (uint32_t)(tid * 4 + mm) * 16, s0r, s0i, cr * SC, sr * SC);
        sincosf(8.0f * t, &stp_i[mm], &stp_r[mm]);
        float s = angle[2 * kk];
        s_mm[mm] = s;
        float f1r_, f1i_, advr_, advi_;
        sincosf(s, &f1i_, &f1r_);
        sincosf(32.0f * s, &advi_, &advr_);
        sts128f(EPI + (uint32_t)(tid * 4 + mm) * 16, f1r_, f1i_, advr_, advi_);
    }
    float run_r[4], run_i[4];
#pragma unroll
    for (int mm = 0; mm < 4; ++mm)
        sincosf(s_mm[mm] * (float)(co0 - 128), &run_i[mm], &run_r[mm]);

    // ---- stage loader ----
    auto issue_load = [&](int st, int buf) {
        int cp_ = st >> 6, ach = (st >> 3) & 7, bq = st & 7;
        const float* src = gX + (size_t)((cp_ * 16 + ach) * 8 + bq) * SLAB;
        uint32_t dst = RING + (uint32_t)buf * STAGEB;
#pragma unroll
        for (int j = 0; j < 6; ++j) {
            int ch  = tid + j * 256;
            int ci  = (ch >= 768) ? 1 : 0;
            int loc = ch - ci * 768;
            int al  = loc / 24;
            int kk2 = loc - al * 24;
            uint32_t doff = (uint32_t)(ci * COILB +
                (kk2 < 16 ? al * SA + kk2 * 16 : ASZ + al * SB + (kk2 - 16) * 16));
            cp16(dst + doff, src + ci * (64 * SLAB) + loc * 4);
        }
        CP_COMMIT();
    };

    float yr[2][4] = {}, yi[2][4] = {};
    issue_load(0, 0);
    int st = 0, buf = 0;

#pragma unroll 1
    for (int cp = 0; cp < 4; ++cp) {
#pragma unroll 1
        for (int ach = 0; ach < 8; ++ach) {
            // reset E2 states from seeds; zero accumulators
            float er_[4][2], ei_[4][2];
#pragma unroll
            for (int mm = 0; mm < 4; ++mm)
                lds128f(er_[mm][0], ei_[mm][0], er_[mm][1], ei_[mm][1],
                        SEEDS + (uint32_t)(tid * 4 + mm) * 16);
            float P1[2][2][4] = {}, P2[2][2][4] = {}, P3[2][2][4] = {};

#pragma unroll 1
            for (int bq = 0; bq < 8; ++bq) {
                CP_WAIT0();
                __syncthreads();
                if (st + 1 < NSTAGE) issue_load(st + 1, buf ^ 1);
                const uint32_t bb = RING + (uint32_t)buf * STAGEB;
                const uint32_t aA = bb + (uint32_t)((ag * 8 + r) * SA) + q * 16;
                const uint32_t aB = bb + ASZ + (uint32_t)((ag * 8 + r) * SB) + q * 8;
#pragma unroll
                for (int bs = 0; bs < 4; ++bs) {
                    uint32_t Ar[2][4], Ai[2][4], As[2][4];
#pragma unroll
                    for (int kw = 0; kw < 2; ++kw) {
                        Ar[kw][0] = __float_as_uint(er_[kw*2][0]);
                        Ar[kw][1] = __float_as_uint(er_[kw*2+1][0]);
                        Ar[kw][2] = __float_as_uint(er_[kw*2][1]);
                        Ar[kw][3] = __float_as_uint(er_[kw*2+1][1]);
                        Ai[kw][0] = __float_as_uint(ei_[kw*2][0]);
                        Ai[kw][1] = __float_as_uint(ei_[kw*2+1][0]);
                        Ai[kw][2] = __float_as_uint(ei_[kw*2][1]);
                        Ai[kw][3] = __float_as_uint(ei_[kw*2+1][1]);
                        As[kw][0] = __float_as_uint(er_[kw*2][0]   + ei_[kw*2][0]);
                        As[kw][1] = __float_as_uint(er_[kw*2+1][0] + ei_[kw*2+1][0]);
                        As[kw][2] = __float_as_uint(er_[kw*2][1]   + ei_[kw*2][1]);
                        As[kw][3] = __float_as_uint(er_[kw*2+1][1] + ei_[kw*2+1][1]);
                    }
#pragma unroll
                    for (int ci = 0; ci < 2; ++ci) {
                        uint32_t xr0, xr1, xi0, xi1, xs0, xs1;
                        lds128(xr0, xr1, xi0, xi1, aA + ci * COILB + bs * 64);
                        lds64(xs0, xs1, aB + ci * COILB + bs * 32);
#pragma unroll
                        for (int kw = 0; kw < 2; ++kw) {
                            mma8(P1[ci][kw], Ar[kw], xr0, xr1);
                            mma8(P2[ci][kw], Ai[kw], xi0, xi1);
                            mma8(P3[ci][kw], As[kw], xs0, xs1);
                        }
                    }
                    // rotate the 8 E2 states by exp(i*8t)
#pragma unroll
                    for (int mm = 0; mm < 4; ++mm)
#pragma unroll
                        for (int o = 0; o < 2; ++o) {
                            float nr = er_[mm][o] * stp_r[mm] - ei_[mm][o] * stp_i[mm];
                            ei_[mm][o] = fmaf(er_[mm][o], stp_i[mm], ei_[mm][o] * stp_r[mm]);
                            er_[mm][o] = nr;
                        }
                }
                ++st; buf ^= 1;
            }

            // ---- epilogue: y += e1 * T (3M combine) ----
            {
                float f1r[4], f1i[4], advr[4], advi[4];
#pragma unroll
                for (int mm = 0; mm < 4; ++mm)
                    lds128f(f1r[mm], f1i[mm], advr[mm], advi[mm],
                            EPI + (uint32_t)(tid * 4 + mm) * 16);
#pragma unroll
                for (int kw = 0; kw < 2; ++kw)
#pragma unroll
                    for (int eh = 0; eh < 2; ++eh) {
                        int mm = kw * 2 + eh;
                        float f0r = run_r[mm], f0i = run_i[mm];
                        float g1r = f0r * f1r[mm] - f0i * f1i[mm];
                        float g1i = f0r * f1i[mm] + f0i * f1r[mm];
#pragma unroll
                        for (int j = 0; j < 2; ++j) {
                            float er2 = j ? g1r : f0r;
                            float ei2 = j ? g1i : f0i;
                            int e = eh * 2 + j;
#pragma unroll
                            for (int ci = 0; ci < 2; ++ci) {
                                float p1 = P1[ci][kw][e], p2 = P2[ci][kw][e];
                                float Tr = p1 - p2;
                                float Ti = P3[ci][kw][e] - p1 - p2;
                                yr[ci][mm] = fmaf(er2, Tr, yr[ci][mm]);
                                yr[ci][mm] = fmaf(-ei2, Ti, yr[ci][mm]);
                                yi[ci][mm] = fmaf(er2, Ti, yi[ci][mm]);
                                yi[ci][mm] = fmaf(ei2, Tr, yi[ci][mm]);
                            }
                        }
                    }
#pragma unroll
                for (int mm = 0; mm < 4; ++mm) {
                    float nr = run_r[mm] * advr[mm] - run_i[mm] * advi[mm];
                    run_i[mm] = fmaf(run_r[mm], advi[mm], run_i[mm] * advr[mm]);
                    run_r[mm] = nr;
                }
            }
        } // ach

        // ---- writeout coil pair cp ----
#pragma unroll
        for (int ci = 0; ci < 2; ++ci)
#pragma unroll
            for (int mm = 0; mm < 4; ++mm) {
                yr[ci][mm] += __shfl_xor_sync(0xffffffffu, yr[ci][mm], 1);
                yr[ci][mm] += __shfl_xor_sync(0xffffffffu, yr[ci][mm], 2);
                yi[ci][mm] += __shfl_xor_sync(0xffffffffu, yi[ci][mm], 1);
                yi[ci][mm] += __shfl_xor_sync(0xffffffffu, yi[ci][mm], 2);
            }
        if (ag > 0 && q == 0) {
#pragma unroll
            for (int ci = 0; ci < 2; ++ci)
#pragma unroll
                for (int mm = 0; mm < 4; ++mm) {
                    int kl = kg * 32 + mm * 8 + r;
                    uint32_t slot = SRED + (uint32_t)(((ag - 1) * 2 + ci) * 64 + kl) * 8;
                    asm volatile("st.shared.v2.f32 [%0], {%1,%2};"
                                 :: "r"(slot), "f"(yr[ci][mm]), "f"(yi[ci][mm]));
                }
        }
        __syncthreads();
        if (ag == 0 && q == 0) {
#pragma unroll
            for (int ci = 0; ci < 2; ++ci)
#pragma unroll
                for (int mm = 0; mm < 4; ++mm) {
                    int kl = kg * 32 + mm * 8 + r;
                    float sr_ = yr[ci][mm], si_ = yi[ci][mm];
#pragma unroll
                    for (int p = 0; p < 3; ++p) {
                        float ar, ai;
                        asm("ld.shared.v2.f32 {%0,%1}, [%2];"
                            : "=f"(ar), "=f"(ai)
                            : "r"(SRED + (uint32_t)((p * 2 + ci) * 64 + kl) * 8));
                        sr_ += ar; si_ += ai;
                    }
                    int k = kblk + kl;
                    float wk = w[k & (NVEC - 1)];
                    size_t o = ((size_t)(cp * 2 + ci) * KTOT + k) * 2;
                    out[o + 0] = sr_ * wk;
                    out[o + 1] = si_ * wk;
                }
        }
        // reset y and run for next coil pair
#pragma unroll
        for (int ci = 0; ci < 2; ++ci)
#pragma unroll
            for (int mm = 0; mm < 4; ++mm) { yr[ci][mm] = 0.f; yi[ci][mm] = 0.f; }
#pragma unroll
        for (int mm = 0; mm < 4; ++mm)
            sincosf(s_mm[mm] * (float)(co0 - 128), &run_i[mm], &run_r[mm]);
    } // cp
}

// ------------------------- launch -------------------------
extern "C" void kernel_launch(void* const* d_in, const int* in_sizes, int n_in,
                              void* d_out, int out_size) {
    const float* input_r = (const float*)d_in[0];
    const float* C_r     = (const float*)d_in[1];
    const float* w       = (const float*)d_in[2];
    const float* angle   = (const float*)d_in[3];
    float* out = (float*)d_out;

    prep_X<<<(NCOIL * NN * NN + 255) / 256, 256>>>(input_r, C_r);

    cudaFuncSetAttribute(main_kernel,
                         cudaFuncAttributeMaxDynamicSharedMemorySize, SMEM_BYTES);
    main_kernel<<<NCTA, 256, SMEM_BYTES>>>(angle, w, out);
}

// round 8
// speedup vs baseline: 1.6775x; 1.6775x over previous
#include <cuda_runtime.h>
#include <cuda_fp16.h>
#include <cstdint>
#include <math.h>

#define NN     256
#define NCOIL  8
#define KTOT   17408
#define NVEC   512
#define KT_CTA 64
#define NCTA   (KTOT / KT_CTA)     // 272

// stage: 2 coils x 32 a-cols x 32 b, fp16
// per coil: RI region 32 cols x 192B (128B data + 64B pad), S region 2KB
#define RIB    6144
#define SBY    2048
#define COILB  (RIB + SBY)         // 8192
#define STAGEB (2 * COILB)         // 16384
#define NBUF   3
#define SMEM_BYTES (NBUF * STAGEB) // 49152
#define NSTAGE 256                 // 4 coil-pairs x 8 ach x 8 bq
#define SLABH  3072                // halves per (coil,ach,bq) slab (6KB)

// packed fp16 Xc blobs, chunk-ordered to match the smem stage layout
__device__ __half gXh[(size_t)NCOIL * 64 * SLABH];

// ------------------------- helpers -------------------------
__device__ __forceinline__ uint32_t smem_u32(const void* p) {
    uint32_t a;
    asm("{ .reg .u64 t; cvta.to.shared.u64 t, %1; cvt.u32.u64 %0, t; }"
        : "=r"(a) : "l"(p));
    return a;
}
__device__ __forceinline__ uint32_t pack2(float lo, float hi) {
    __half2 h = __floats2half2_rn(lo, hi);   // .x (low) = lo
    return *reinterpret_cast<uint32_t*>(&h);
}
__device__ __forceinline__ void cp16(uint32_t dst, const void* src) {
    asm volatile("cp.async.cg.shared.global [%0], [%1], 16;"
                 :: "r"(dst), "l"(src) : "memory");
}
#define CP_COMMIT() asm volatile("cp.async.commit_group;" ::: "memory")
#define CP_WAIT(n)  asm volatile("cp.async.wait_group %0;" :: "n"(n) : "memory")

__device__ __forceinline__ void lds128(uint32_t& a, uint32_t& b, uint32_t& c,
                                       uint32_t& d, uint32_t addr) {
    asm("ld.shared.v4.b32 {%0,%1,%2,%3}, [%4];"
        : "=r"(a), "=r"(b), "=r"(c), "=r"(d) : "r"(addr));
}
__device__ __forceinline__ void lds64(uint32_t& a, uint32_t& b, uint32_t addr) {
    asm("ld.shared.v2.b32 {%0,%1}, [%2];" : "=r"(a), "=r"(b) : "r"(addr));
}
// fp16 m16n8k16 mma, fp32 accumulate
__device__ __forceinline__ void mma16(float* d, const uint32_t* A,
                                      uint32_t b0, uint32_t b1) {
    asm volatile(
        "mma.sync.aligned.m16n8k16.row.col.f32.f16.f16.f32 "
        "{%0,%1,%2,%3}, {%4,%5,%6,%7}, {%8,%9}, {%0,%1,%2,%3};"
        : "+f"(d[0]), "+f"(d[1]), "+f"(d[2]), "+f"(d[3])
        : "r"(A[0]), "r"(A[1]), "r"(A[2]), "r"(A[3]), "r"(b0), "r"(b1));
}

// ------------------------- prep -------------------------
__global__ void prep_X(const float* __restrict__ input_r,
                       const float* __restrict__ C_r) {
    int idx = blockIdx.x * blockDim.x + threadIdx.x;   // (c*256+a)*256 + b
    if (idx >= NCOIL * NN * NN) return;
    int c = idx >> 16;
    int a = (idx >> 8) & 255;
    int b = idx & 255;
    float xr = input_r[(a * NN + b) * 2 + 0];
    float xi = input_r[(a * NN + b) * 2 + 1];
    float cr = C_r[(size_t)idx * 2 + 0];
    float ci = C_r[(size_t)idx * 2 + 1];
    float Xr = cr * xr - ci * xi;
    float Xi = cr * xi + ci * xr;

    int ach = a >> 5, col = a & 31;
    int bq = b >> 5, bl = b & 31;
    int blk = bl >> 4, kk = bl & 15;
    int hi = kk >> 3, q = (kk & 7) >> 1, part = kk & 1;

    size_t base = ((size_t)c * 64 + ach * 8 + bq) * SLABH;
    int chA = col * 8 + blk * 4 + q;           // RI chunk index
    gXh[base + chA * 8 + 0 + hi * 2 + part] = __float2half_rn(Xr);
    gXh[base + chA * 8 + 4 + hi * 2 + part] = __float2half_rn(Xi);
    gXh[base + 2048 + blk * 512 + col * 16 + q * 4 + hi * 2 + part] =
        __float2half_rn(Xr + Xi);
}

// ------------------------- main -------------------------
extern __shared__ char dyn_smem[];

__global__ void __launch_bounds__(256, 2)
main_kernel(const float* __restrict__ angle, const float* __restrict__ w,
            float* __restrict__ out) {
    __shared__ float2 sred[2][KT_CTA];

    const uint32_t XST = smem_u32(dyn_smem);
    const int tid  = threadIdx.x;
    const int lane = tid & 31;
    const int warp = tid >> 5;
    const int kw   = warp & 3;        // k-subtile (16 rows)
    const int nw   = warp >> 2;       // a-half (16 cols)
    const int r    = lane >> 2;
    const int q    = lane & 3;
    const int kblk = blockIdx.x * KT_CTA;

    const int k0g = kblk + kw * 16 + r;       // MMA row r
    const int k1g = k0g + 8;                  // MMA row r+8
    const float t0 = angle[2 * k0g + 1];
    const float t1 = angle[2 * k1g + 1];

    // E2 seeds: states [m][o] at b = 2q (o=0) and 2q+8 (o=1), start b-128
    float sd_r[2][2], sd_i[2][2];
    sincosf(t0 * (float)(2 * q - 128),     &sd_i[0][0], &sd_r[0][0]);
    sincosf(t0 * (float)(2 * q - 120),     &sd_i[0][1], &sd_r[0][1]);
    sincosf(t1 * (float)(2 * q - 128),     &sd_i[1][0], &sd_r[1][0]);
    sincosf(t1 * (float)(2 * q - 120),     &sd_i[1][1], &sd_r[1][1]);
    float r1r[2], r1i[2], st16r[2], st16i[2];   // neighbor exp(i t), step exp(i 16t)
    sincosf(t0, &r1i[0], &r1r[0]);
    sincosf(t1, &r1i[1], &r1r[1]);
    sincosf(16.0f * t0, &st16i[0], &st16r[0]);
    sincosf(16.0f * t1, &st16i[1], &st16r[1]);

    // E1 epilogue constants
    const float s0 = angle[2 * k0g];
    const float s1 = angle[2 * k1g];
    float sttr[2], stti[2], advr[2], advi[2];
    float fc0r[2], fc0i[2], f1r[2], f1i[2], f8r[2], f8i[2];
    {
        const float ss[2] = {s0, s1};
        const int co0 = nw * 16 + 2 * q;
#pragma unroll
        for (int m = 0; m < 2; ++m) {
            sincosf(-128.0f * ss[m], &stti[m], &sttr[m]);
            sincosf(32.0f * ss[m], &advi[m], &advr[m]);
            sincosf(ss[m] * (float)co0, &fc0i[m], &fc0r[m]);
            sincosf(ss[m], &f1i[m], &f1r[m]);
            sincosf(8.0f * ss[m], &f8i[m], &f8r[m]);
        }
    }
    const float wk0 = w[k0g & (NVEC - 1)];
    const float wk1 = w[k1g & (NVEC - 1)];

    // loader: 768 16B-chunks/stage, 3 per thread
    auto issue_load = [&](int st, int buf) {
        int cp_ = st >> 6, ach = (st >> 3) & 7, bq = st & 7;
        const char* src =
            (const char*)(gXh + (size_t)((cp_ * 16 + ach) * 8 + bq) * SLABH);
        uint32_t dst = XST + (uint32_t)buf * STAGEB;
#pragma unroll
        for (int j = 0; j < 3; ++j) {
            int ch  = tid + j * 256;
            int ci  = (ch >= 384) ? 1 : 0;
            int loc = ch - ci * 384;
            uint32_t doff;
            if (loc < 256) {
                int col = loc >> 3, blk = (loc >> 2) & 1, qq = loc & 3;
                doff = (uint32_t)(ci * COILB + col * 192 + blk * 64 + qq * 16);
            } else {
                int s2 = loc - 256;
                int blk = s2 >> 6, col = (s2 >> 1) & 31, qp = s2 & 1;
                doff = (uint32_t)(ci * COILB + RIB + blk * 1024 + col * 32 + qp * 16);
            }
            cp16(dst + doff, src + (size_t)ci * (64 * SLABH * 2) + loc * 16);
        }
        CP_COMMIT();
    };

    float yr[2][2] = {}, yi[2][2] = {};
    float runr[2] = {sttr[0], sttr[1]}, runi[2] = {stti[0], stti[1]};

    issue_load(0, 0);
    issue_load(1, 1);
    int st = 0, buf = 0;

#pragma unroll 1
    for (int cp = 0; cp < 4; ++cp) {
#pragma unroll 1
        for (int ach = 0; ach < 8; ++ach) {
            float er_[2][2], ei_[2][2];
#pragma unroll
            for (int m = 0; m < 2; ++m)
#pragma unroll
                for (int o = 0; o < 2; ++o) {
                    er_[m][o] = sd_r[m][o];
                    ei_[m][o] = sd_i[m][o];
                }
            float P1[2][2][4] = {}, P2[2][2][4] = {}, P3[2][2][4] = {};

#pragma unroll 1
            for (int bq = 0; bq < 8; ++bq) {
                CP_WAIT(1);
                __syncthreads();
                {
                    int nb = buf + 2; if (nb >= 3) nb -= 3;
                    if (st + 2 < NSTAGE) issue_load(st + 2, nb);
                    else                 CP_COMMIT();
                }
                const uint32_t bb  = XST + (uint32_t)buf * STAGEB;
                const uint32_t riB = bb + (uint32_t)(nw * 16 + r) * 192 + q * 16;
                const uint32_t sB  = bb + RIB + (uint32_t)(nw * 16 + r) * 32 + q * 8;
#pragma unroll
                for (int blk = 0; blk < 2; ++blk) {
                    // build fp16 A fragments from rotation states
                    uint32_t Ar[4], Ai[4], As[4];
#pragma unroll
                    for (int o = 0; o < 2; ++o)
#pragma unroll
                        for (int m = 0; m < 2; ++m) {
                            float br = er_[m][o], bi = ei_[m][o];
                            float nr2 = br * r1r[m] - bi * r1i[m];
                            float ni2 = br * r1i[m] + bi * r1r[m];
                            int idx = o * 2 + m;
                            Ar[idx] = pack2(br, nr2);
                            Ai[idx] = pack2(bi, ni2);
                            As[idx] = pack2(br + bi, nr2 + ni2);
                        }
#pragma unroll
                    for (int ci = 0; ci < 2; ++ci)
#pragma unroll
                        for (int nt = 0; nt < 2; ++nt) {
                            uint32_t rlo, rhi, ilo, ihi, slo, shi;
                            lds128(rlo, rhi, ilo, ihi,
                                   riB + ci * COILB + nt * (8 * 192) + blk * 64);
                            lds64(slo, shi,
                                  sB + ci * COILB + nt * (8 * 32) + blk * 1024);
                            mma16(P1[ci][nt], Ar, rlo, rhi);
                            mma16(P2[ci][nt], Ai, ilo, ihi);
                            mma16(P3[ci][nt], As, slo, shi);
                        }
                    // rotate states by exp(i*16t)
#pragma unroll
                    for (int m = 0; m < 2; ++m)
#pragma unroll
                        for (int o = 0; o < 2; ++o) {
                            float nr2 = er_[m][o] * st16r[m] - ei_[m][o] * st16i[m];
                            ei_[m][o] = fmaf(er_[m][o], st16i[m], ei_[m][o] * st16r[m]);
                            er_[m][o] = nr2;
                        }
                }
                ++st; ++buf; if (buf == 3) buf = 0;
            }

            // ---- epilogue: y += e1 * T (3M combine) ----
#pragma unroll
            for (int m = 0; m < 2; ++m) {
                float b0r = runr[m] * fc0r[m] - runi[m] * fc0i[m];
                float b0i = runr[m] * fc0i[m] + runi[m] * fc0r[m];
#pragma unroll
                for (int nt = 0; nt < 2; ++nt) {
                    float cr_ = b0r, ci_ = b0i;
                    if (nt == 1) {
                        cr_ = b0r * f8r[m] - b0i * f8i[m];
                        ci_ = b0r * f8i[m] + b0i * f8r[m];
                    }
#pragma unroll
                    for (int j = 0; j < 2; ++j) {
                        float er2 = cr_, ei2 = ci_;
                        if (j == 1) {
                            er2 = cr_ * f1r[m] - ci_ * f1i[m];
                            ei2 = cr_ * f1i[m] + ci_ * f1r[m];
                        }
                        int e = m * 2 + j;
#pragma unroll
                        for (int ci2 = 0; ci2 < 2; ++ci2) {
                            float p1 = P1[ci2][nt][e], p2 = P2[ci2][nt][e];
                            float Tr = p1 - p2;
                            float Ti = P3[ci2][nt][e] - p1 - p2;
                            yr[ci2][m] = fmaf(er2, Tr, yr[ci2][m]);
                            yr[ci2][m] = fmaf(-ei2, Ti, yr[ci2][m]);
                            yi[ci2][m] = fmaf(er2, Ti, yi[ci2][m]);
                            yi[ci2][m] = fmaf(ei2, Tr, yi[ci2][m]);
                        }
                    }
                }
            }
#pragma unroll
            for (int m = 0; m < 2; ++m) {
                float nr2 = runr[m] * advr[m] - runi[m] * advi[m];
                runi[m] = fmaf(runr[m], advi[m], runi[m] * advr[m]);
                runr[m] = nr2;
            }
        } // ach

        // ---- writeout coil pair cp ----
#pragma unroll
        for (int ci = 0; ci < 2; ++ci)
#pragma unroll
            for (int m = 0; m < 2; ++m) {
                yr[ci][m] += __shfl_xor_sync(0xffffffffu, yr[ci][m], 1);
                yr[ci][m] += __shfl_xor_sync(0xffffffffu, yr[ci][m], 2);
                yi[ci][m] += __shfl_xor_sync(0xffffffffu, yi[ci][m], 1);
                yi[ci][m] += __shfl_xor_sync(0xffffffffu, yi[ci][m], 2);
            }
        if (nw == 1 && q == 0) {
            sred[0][kw * 16 + r]     = make_float2(yr[0][0], yi[0][0]);
            sred[0][kw * 16 + 8 + r] = make_float2(yr[0][1], yi[0][1]);
            sred[1][kw * 16 + r]     = make_float2(yr[1][0], yi[1][0]);
            sred[1][kw * 16 + 8 + r] = make_float2(yr[1][1], yi[1][1]);
        }
        __syncthreads();
        if (nw == 0 && q == 0) {
            int c0 = cp * 2;
#pragma unroll
            for (int ci = 0; ci < 2; ++ci) {
                float2 p0 = sred[ci][kw * 16 + r];
                float2 p1 = sred[ci][kw * 16 + 8 + r];
                size_t o0 = ((size_t)(c0 + ci) * KTOT + k0g) * 2;
                size_t o1 = ((size_t)(c0 + ci) * KTOT + k1g) * 2;
                out[o0 + 0] = (yr[ci][0] + p0.x) * wk0;
                out[o0 + 1] = (yi[ci][0] + p0.y) * wk0;
                out[o1 + 0] = (yr[ci][1] + p1.x) * wk1;
                out[o1 + 1] = (yi[ci][1] + p1.y) * wk1;
            }
        }
#pragma unroll
        for (int ci = 0; ci < 2; ++ci)
#pragma unroll
            for (int m = 0; m < 2; ++m) { yr[ci][m] = 0.f; yi[ci][m] = 0.f; }
#pragma unroll
        for (int m = 0; m < 2; ++m) { runr[m] = sttr[m]; runi[m] = stti[m]; }
    } // cp
}

// ------------------------- launch -------------------------
extern "C" void kernel_launch(void* const* d_in, const int* in_sizes, int n_in,
                              void* d_out, int out_size) {
    const float* input_r = (const float*)d_in[0];
    const float* C_r     = (const float*)d_in[1];
    const float* w       = (const float*)d_in[2];
    const float* angle   = (const float*)d_in[3];
    float* out = (float*)d_out;

    prep_X<<<(NCOIL * NN * NN + 255) / 256, 256>>>(input_r, C_r);

    cudaFuncSetAttribute(main_kernel,
                         cudaFuncAttributeMaxDynamicSharedMemorySize, SMEM_BYTES);
    main_kernel<<<NCTA, 256, SMEM_BYTES>>>(angle, w, out);
}

// round 9
// speedup vs baseline: 2.1299x; 1.2696x over previous
#include <cuda_runtime.h>
#include <cuda_fp16.h>
#include <cstdint>
#include <math.h>

#define NN     256
#define NCOIL  8
#define KTOT   17408
#define NVEC   512
#define KT_CTA 64
#define NCTA   (KTOT / KT_CTA)     // 272

// stage: 2 coils x 32 a-cols x 32 b, fp16, R+I planes only
// per coil: 32 cols x 192B (128B data + 64B pad)
#define COILB  6144
#define STAGEB (2 * COILB)         // 12288
#define NBUF   3
#define RINGB  (NBUF * STAGEB)     // 36864
#define TBLB   65536               // E2 fragment table: 4kw x 8bq x 2blk x 2pl x 512B
#define SMEM_BYTES (RINGB + TBLB)  // 102400
#define NSTAGE 256                 // 4 coil-pairs x 8 ach x 8 bq
#define SLABH  2048                // halves per (coil,ach,bq) slab (4KB)

// packed fp16 Xc blobs (R/I chunks), ordered to match the smem stage layout
__device__ __half gXh[(size_t)NCOIL * 64 * SLABH];

// ------------------------- helpers -------------------------
__device__ __forceinline__ uint32_t smem_u32(const void* p) {
    uint32_t a;
    asm("{ .reg .u64 t; cvta.to.shared.u64 t, %1; cvt.u32.u64 %0, t; }"
        : "=r"(a) : "l"(p));
    return a;
}
__device__ __forceinline__ uint32_t pack2(float lo, float hi) {
    __half2 h = __floats2half2_rn(lo, hi);
    return *reinterpret_cast<uint32_t*>(&h);
}
__device__ __forceinline__ uint32_t hadd2u(uint32_t a, uint32_t b) {
    uint32_t d;
    asm("add.f16x2 %0, %1, %2;" : "=r"(d) : "r"(a), "r"(b));
    return d;
}
__device__ __forceinline__ void cp16(uint32_t dst, const void* src) {
    asm volatile("cp.async.cg.shared.global [%0], [%1], 16;"
                 :: "r"(dst), "l"(src) : "memory");
}
#define CP_COMMIT() asm volatile("cp.async.commit_group;" ::: "memory")
#define CP_WAIT(n)  asm volatile("cp.async.wait_group %0;" :: "n"(n) : "memory")

__device__ __forceinline__ void lds128(uint32_t& a, uint32_t& b, uint32_t& c,
                                       uint32_t& d, uint32_t addr) {
    asm("ld.shared.v4.b32 {%0,%1,%2,%3}, [%4];"
        : "=r"(a), "=r"(b), "=r"(c), "=r"(d) : "r"(addr));
}
__device__ __forceinline__ void sts128(uint32_t addr, const uint32_t* v) {
    asm volatile("st.shared.v4.b32 [%0], {%1,%2,%3,%4};"
                 :: "r"(addr), "r"(v[0]), "r"(v[1]), "r"(v[2]), "r"(v[3]));
}
// fp16 m16n8k16 mma, fp32 accumulate
__device__ __forceinline__ void mma16(float* d, const uint32_t* A,
                                      uint32_t b0, uint32_t b1) {
    asm volatile(
        "mma.sync.aligned.m16n8k16.row.col.f32.f16.f16.f32 "
        "{%0,%1,%2,%3}, {%4,%5,%6,%7}, {%8,%9}, {%0,%1,%2,%3};"
        : "+f"(d[0]), "+f"(d[1]), "+f"(d[2]), "+f"(d[3])
        : "r"(A[0]), "r"(A[1]), "r"(A[2]), "r"(A[3]), "r"(b0), "r"(b1));
}

// ------------------------- prep -------------------------
__global__ void prep_X(const float* __restrict__ input_r,
                       const float* __restrict__ C_r) {
    int idx = blockIdx.x * blockDim.x + threadIdx.x;   // (c*256+a)*256 + b
    if (idx >= NCOIL * NN * NN) return;
    int c = idx >> 16;
    int a = (idx >> 8) & 255;
    int b = idx & 255;
    float xr = input_r[(a * NN + b) * 2 + 0];
    float xi = input_r[(a * NN + b) * 2 + 1];
    float cr = C_r[(size_t)idx * 2 + 0];
    float ci = C_r[(size_t)idx * 2 + 1];
    float Xr = cr * xr - ci * xi;
    float Xi = cr * xi + ci * xr;

    int ach = a >> 5, col = a & 31;
    int bq = b >> 5, bl = b & 31;
    int blk = bl >> 4, kk = bl & 15;
    int hi = kk >> 3, q = (kk & 7) >> 1, part = kk & 1;

    size_t base = ((size_t)c * 64 + ach * 8 + bq) * SLABH;
    int chA = col * 8 + blk * 4 + q;
    gXh[base + chA * 8 + 0 + hi * 2 + part] = __float2half_rn(Xr);
    gXh[base + chA * 8 + 4 + hi * 2 + part] = __float2half_rn(Xi);
}

// ------------------------- main -------------------------
extern __shared__ char dyn_smem[];

__global__ void __launch_bounds__(256, 2)
main_kernel(const float* __restrict__ angle, const float* __restrict__ w,
            float* __restrict__ out) {
    __shared__ float2 sred[2][KT_CTA];

    const uint32_t XST = smem_u32(dyn_smem);
    const uint32_t TBL = XST + RINGB;
    const int tid  = threadIdx.x;
    const int lane = tid & 31;
    const int warp = tid >> 5;
    const int kw   = warp & 3;        // k-subtile (16 rows)
    const int nw   = warp >> 2;       // a-half (16 cols)
    const int r    = lane >> 2;
    const int q    = lane & 3;
    const int kblk = blockIdx.x * KT_CTA;

    const int k0g = kblk + kw * 16 + r;       // MMA row r
    const int k1g = k0g + 8;                  // MMA row r+8
    const float t0 = angle[2 * k0g + 1];
    const float t1 = angle[2 * k1g + 1];

    // E1 epilogue constants
    const float s0 = angle[2 * k0g];
    const float s1 = angle[2 * k1g];
    float sttr[2], stti[2], advr[2], advi[2];
    float fc0r[2], fc0i[2], f1r[2], f1i[2], f8r[2], f8i[2];
    {
        const float ss[2] = {s0, s1};
        const int co0 = nw * 16 + 2 * q;
#pragma unroll
        for (int m = 0; m < 2; ++m) {
            sincosf(-128.0f * ss[m], &stti[m], &sttr[m]);
            sincosf(32.0f * ss[m], &advi[m], &advr[m]);
            sincosf(ss[m] * (float)co0, &fc0i[m], &fc0r[m]);
            sincosf(ss[m], &f1i[m], &f1r[m]);
            sincosf(8.0f * ss[m], &f8i[m], &f8r[m]);
        }
    }
    const float wk0 = w[k0g & (NVEC - 1)];
    const float wk1 = w[k1g & (NVEC - 1)];

    // loader: 512 16B-chunks/stage, 2 per thread
    auto issue_load = [&](int st, int buf) {
        int cp_ = st >> 6, ach = (st >> 3) & 7, bq = st & 7;
        const char* src =
            (const char*)(gXh + (size_t)((cp_ * 16 + ach) * 8 + bq) * SLABH);
        uint32_t dst = XST + (uint32_t)buf * STAGEB;
#pragma unroll
        for (int j = 0; j < 2; ++j) {
            int ch  = tid + j * 256;
            int ci  = ch >> 8;
            int loc = ch & 255;
            int col = loc >> 3, blk = (loc >> 2) & 1, qq = loc & 3;
            uint32_t doff = (uint32_t)(ci * COILB + col * 192 + blk * 64 + qq * 16);
            cp16(dst + doff, src + (size_t)ci * (64 * SLABH * 2) + loc * 16);
        }
        CP_COMMIT();
    };

    issue_load(0, 0);
    issue_load(1, 1);

    // ---- generate E2 fragment table (once per CTA; nw==0 warps) ----
    if (nw == 0) {
        float er_[2][2], ei_[2][2];
        sincosf(t0 * (float)(2 * q - 128), &ei_[0][0], &er_[0][0]);
        sincosf(t0 * (float)(2 * q - 120), &ei_[0][1], &er_[0][1]);
        sincosf(t1 * (float)(2 * q - 128), &ei_[1][0], &er_[1][0]);
        sincosf(t1 * (float)(2 * q - 120), &ei_[1][1], &er_[1][1]);
        float r1r[2], r1i[2], st16r[2], st16i[2];
        sincosf(t0, &r1i[0], &r1r[0]);
        sincosf(t1, &r1i[1], &r1r[1]);
        sincosf(16.0f * t0, &st16i[0], &st16r[0]);
        sincosf(16.0f * t1, &st16i[1], &st16r[1]);

        uint32_t ga = TBL + (uint32_t)kw * 16384 + (uint32_t)lane * 16;
#pragma unroll 4
        for (int bb2 = 0; bb2 < 16; ++bb2) {
            uint32_t Ar[4], Ai[4];
#pragma unroll
            for (int o = 0; o < 2; ++o)
#pragma unroll
                for (int m = 0; m < 2; ++m) {
                    float br = er_[m][o], bi = ei_[m][o];
                    float nr2 = br * r1r[m] - bi * r1i[m];
                    float ni2 = br * r1i[m] + bi * r1r[m];
                    int idx = o * 2 + m;
                    Ar[idx] = pack2(br, nr2);
                    Ai[idx] = pack2(bi, ni2);
                }
            sts128(ga, Ar);
            sts128(ga + 512, Ai);
            ga += 1024;
#pragma unroll
            for (int m = 0; m < 2; ++m)
#pragma unroll
                for (int o = 0; o < 2; ++o) {
                    float nr2 = er_[m][o] * st16r[m] - ei_[m][o] * st16i[m];
                    ei_[m][o] = fmaf(er_[m][o], st16i[m], ei_[m][o] * st16r[m]);
                    er_[m][o] = nr2;
                }
        }
    }

    float yr[2][2] = {}, yi[2][2] = {};
    float runr[2] = {sttr[0], sttr[1]}, runi[2] = {stti[0], stti[1]};

    const uint32_t TA0 = TBL + (uint32_t)kw * 16384 + (uint32_t)lane * 16;
    int st = 0, buf = 0;

#pragma unroll 1
    for (int cp = 0; cp < 4; ++cp) {
#pragma unroll 1
        for (int ach = 0; ach < 8; ++ach) {
            float P1[2][2][4] = {}, P2[2][2][4] = {}, P3[2][2][4] = {};

#pragma unroll 1
            for (int bq = 0; bq < 8; ++bq) {
                CP_WAIT(1);
                __syncthreads();
                {
                    int nb = buf + 2; if (nb >= 3) nb -= 3;
                    if (st + 2 < NSTAGE) issue_load(st + 2, nb);
                    else                 CP_COMMIT();
                }
                const uint32_t bb  = XST + (uint32_t)buf * STAGEB;
                const uint32_t riB = bb + (uint32_t)(nw * 16 + r) * 192 + q * 16;
                const uint32_t TA  = TA0 + (uint32_t)bq * 2048;
#pragma unroll
                for (int blk = 0; blk < 2; ++blk) {
                    uint32_t Ar[4], Ai[4], As[4];
                    lds128(Ar[0], Ar[1], Ar[2], Ar[3], TA + blk * 1024);
                    lds128(Ai[0], Ai[1], Ai[2], Ai[3], TA + blk * 1024 + 512);
#pragma unroll
                    for (int j = 0; j < 4; ++j) As[j] = hadd2u(Ar[j], Ai[j]);
#pragma unroll
                    for (int ci = 0; ci < 2; ++ci)
#pragma unroll
                        for (int nt = 0; nt < 2; ++nt) {
                            uint32_t rlo, rhi, ilo, ihi;
                            lds128(rlo, rhi, ilo, ihi,
                                   riB + ci * COILB + nt * (8 * 192) + blk * 64);
                            uint32_t slo = hadd2u(rlo, ilo);
                            uint32_t shi = hadd2u(rhi, ihi);
                            mma16(P1[ci][nt], Ar, rlo, rhi);
                            mma16(P2[ci][nt], Ai, ilo, ihi);
                            mma16(P3[ci][nt], As, slo, shi);
                        }
                }
                ++st; ++buf; if (buf == 3) buf = 0;
            }

            // ---- epilogue: y += e1 * T (3M combine) ----
#pragma unroll
            for (int m = 0; m < 2; ++m) {
                float b0r = runr[m] * fc0r[m] - runi[m] * fc0i[m];
                float b0i = runr[m] * fc0i[m] + runi[m] * fc0r[m];
#pragma unroll
                for (int nt = 0; nt < 2; ++nt) {
                    float cr_ = b0r, ci_ = b0i;
                    if (nt == 1) {
                        cr_ = b0r * f8r[m] - b0i * f8i[m];
                        ci_ = b0r * f8i[m] + b0i * f8r[m];
                    }
#pragma unroll
                    for (int j = 0; j < 2; ++j) {
                        float er2 = cr_, ei2 = ci_;
                        if (j == 1) {
                            er2 = cr_ * f1r[m] - ci_ * f1i[m];
                            ei2 = cr_ * f1i[m] + ci_ * f1r[m];
                        }
                        int e = m * 2 + j;
#pragma unroll
                        for (int ci2 = 0; ci2 < 2; ++ci2) {
                            float p1 = P1[ci2][nt][e], p2 = P2[ci2][nt][e];
                            float Tr = p1 - p2;
                            float Ti = P3[ci2][nt][e] - p1 - p2;
                            yr[ci2][m] = fmaf(er2, Tr, yr[ci2][m]);
                            yr[ci2][m] = fmaf(-ei2, Ti, yr[ci2][m]);
                            yi[ci2][m] = fmaf(er2, Ti, yi[ci2][m]);
                            yi[ci2][m] = fmaf(ei2, Tr, yi[ci2][m]);
                        }
                    }
                }
            }
#pragma unroll
            for (int m = 0; m < 2; ++m) {
                float nr2 = runr[m] * advr[m] - runi[m] * advi[m];
                runi[m] = fmaf(runr[m], advi[m], runi[m] * advr[m]);
                runr[m] = nr2;
            }
        } // ach

        // ---- writeout coil pair cp ----
#pragma unroll
        for (int ci = 0; ci < 2; ++ci)
#pragma unroll
            for (int m = 0; m < 2; ++m) {
                yr[ci][m] += __shfl_xor_sync(0xffffffffu, yr[ci][m], 1);
                yr[ci][m] += __shfl_xor_sync(0xffffffffu, yr[ci][m], 2);
                yi[ci][m] += __shfl_xor_sync(0xffffffffu, yi[ci][m], 1);
                yi[ci][m] += __shfl_xor_sync(0xffffffffu, yi[ci][m], 2);
            }
        if (nw == 1 && q == 0) {
            sred[0][kw * 16 + r]     = make_float2(yr[0][0], yi[0][0]);
            sred[0][kw * 16 + 8 + r] = make_float2(yr[0][1], yi[0][1]);
            sred[1][kw * 16 + r]     = make_float2(yr[1][0], yi[1][0]);
            sred[1][kw * 16 + 8 + r] = make_float2(yr[1][1], yi[1][1]);
        }
        __syncthreads();
        if (nw == 0 && q == 0) {
            int c0 = cp * 2;
#pragma unroll
            for (int ci = 0; ci < 2; ++ci) {
                float2 p0 = sred[ci][kw * 16 + r];
                float2 p1 = sred[ci][kw * 16 + 8 + r];
                size_t o0 = ((size_t)(c0 + ci) * KTOT + k0g) * 2;
                size_t o1 = ((size_t)(c0 + ci) * KTOT + k1g) * 2;
                out[o0 + 0] = (yr[ci][0] + p0.x) * wk0;
                out[o0 + 1] = (yi[ci][0] + p0.y) * wk0;
                out[o1 + 0] = (yr[ci][1] + p1.x) * wk1;
                out[o1 + 1] = (yi[ci][1] + p1.y) * wk1;
            }
        }
#pragma unroll
        for (int ci = 0; ci < 2; ++ci)
#pragma unroll
            for (int m = 0; m < 2; ++m) { yr[ci][m] = 0.f; yi[ci][m] = 0.f; }
#pragma unroll
        for (int m = 0; m < 2; ++m) { runr[m] = sttr[m]; runi[m] = stti[m]; }
    } // cp
}

// ------------------------- launch -------------------------
extern "C" void kernel_launch(void* const* d_in, const int* in_sizes, int n_in,
                              void* d_out, int out_size) {
    const float* input_r = (const float*)d_in[0];
    const float* C_r     = (const float*)d_in[1];
    const float* w       = (const float*)d_in[2];
    const float* angle   = (const float*)d_in[3];
    float* out = (float*)d_out;

    prep_X<<<(NCOIL * NN * NN + 255) / 256, 256>>>(input_r, C_r);

    cudaFuncSetAttribute(main_kernel,
                         cudaFuncAttributeMaxDynamicSharedMemorySize, SMEM_BYTES);
    main_kernel<<<NCTA, 256, SMEM_BYTES>>>(angle, w, out);
}

// round 10
// speedup vs baseline: 2.3817x; 1.1183x over previous
#include <cuda_runtime.h>
#include <cuda_fp16.h>
#include <cstdint>
#include <math.h>

#define NN     256
#define NCOIL  8
#define KTOT   17408
#define NVEC   512
#define KT_CTA 64
#define NCTA   (KTOT / KT_CTA)     // 272

// stage: 2 coils x 32 a-cols x 32 b, fp16, parity-swizzled (no padding)
#define COILB  4096                // 32 cols x 128B
#define STAGEB (2 * COILB)         // 8192
#define NBUF   4
#define RINGB  (NBUF * STAGEB)     // 32768
#define TBLB   65536               // E2 fragment table
#define SMEM_BYTES (RINGB + TBLB)  // 98304
#define NSTAGE 256                 // 4 coil-pairs x 8 ach x 8 bq
#define SLABH  2048                // halves per (coil,ach,bq) slab (4KB)

// packed fp16 Xc blobs (R/I chunks), chunk idx = col*8 + blk*4 + q
__device__ __half gXh[(size_t)NCOIL * 64 * SLABH];

// ------------------------- helpers -------------------------
__device__ __forceinline__ uint32_t smem_u32(const void* p) {
    uint32_t a;
    asm("{ .reg .u64 t; cvta.to.shared.u64 t, %1; cvt.u32.u64 %0, t; }"
        : "=r"(a) : "l"(p));
    return a;
}
__device__ __forceinline__ uint32_t pack2(float lo, float hi) {
    __half2 h = __floats2half2_rn(lo, hi);
    return *reinterpret_cast<uint32_t*>(&h);
}
__device__ __forceinline__ uint32_t hadd2u(uint32_t a, uint32_t b) {
    uint32_t d;
    asm("add.f16x2 %0, %1, %2;" : "=r"(d) : "r"(a), "r"(b));
    return d;
}
__device__ __forceinline__ void cp16(uint32_t dst, const void* src) {
    asm volatile("cp.async.cg.shared.global [%0], [%1], 16;"
                 :: "r"(dst), "l"(src) : "memory");
}
#define CP_COMMIT() asm volatile("cp.async.commit_group;" ::: "memory")
#define CP_WAIT0()  asm volatile("cp.async.wait_group 0;" ::: "memory")

__device__ __forceinline__ void lds128(uint32_t& a, uint32_t& b, uint32_t& c,
                                       uint32_t& d, uint32_t addr) {
    asm("ld.shared.v4.b32 {%0,%1,%2,%3}, [%4];"
        : "=r"(a), "=r"(b), "=r"(c), "=r"(d) : "r"(addr));
}
__device__ __forceinline__ void sts128(uint32_t addr, const uint32_t* v) {
    asm volatile("st.shared.v4.b32 [%0], {%1,%2,%3,%4};"
                 :: "r"(addr), "r"(v[0]), "r"(v[1]), "r"(v[2]), "r"(v[3]));
}
// fp16 m16n8k16 mma, fp32 accumulate
__device__ __forceinline__ void mma16(float* d, const uint32_t* A,
                                      uint32_t b0, uint32_t b1) {
    asm volatile(
        "mma.sync.aligned.m16n8k16.row.col.f32.f16.f16.f32 "
        "{%0,%1,%2,%3}, {%4,%5,%6,%7}, {%8,%9}, {%0,%1,%2,%3};"
        : "+f"(d[0]), "+f"(d[1]), "+f"(d[2]), "+f"(d[3])
        : "r"(A[0]), "r"(A[1]), "r"(A[2]), "r"(A[3]), "r"(b0), "r"(b1));
}

// ------------------------- prep -------------------------
__global__ void prep_X(const float* __restrict__ input_r,
                       const float* __restrict__ C_r) {
    int idx = blockIdx.x * blockDim.x + threadIdx.x;   // (c*256+a)*256 + b
    if (idx >= NCOIL * NN * NN) return;
    int c = idx >> 16;
    int a = (idx >> 8) & 255;
    int b = idx & 255;
    float xr = input_r[(a * NN + b) * 2 + 0];
    float xi = input_r[(a * NN + b) * 2 + 1];
    float cr = C_r[(size_t)idx * 2 + 0];
    float ci = C_r[(size_t)idx * 2 + 1];
    float Xr = cr * xr - ci * xi;
    float Xi = cr * xi + ci * xr;

    int ach = a >> 5, col = a & 31;
    int bq = b >> 5, bl = b & 31;
    int blk = bl >> 4, kk = bl & 15;
    int hi = kk >> 3, q = (kk & 7) >> 1, part = kk & 1;

    size_t base = ((size_t)c * 64 + ach * 8 + bq) * SLABH;
    int chA = col * 8 + blk * 4 + q;
    gXh[base + chA * 8 + 0 + hi * 2 + part] = __float2half_rn(Xr);
    gXh[base + chA * 8 + 4 + hi * 2 + part] = __float2half_rn(Xi);
}

// ------------------------- main -------------------------
extern __shared__ char dyn_smem[];

__global__ void __launch_bounds__(256, 2)
main_kernel(const float* __restrict__ angle, const float* __restrict__ w,
            float* __restrict__ out) {
    __shared__ float2 sred[2][KT_CTA];

    const uint32_t XST = smem_u32(dyn_smem);
    const uint32_t TBL = XST + RINGB;
    const int tid  = threadIdx.x;
    const int lane = tid & 31;
    const int warp = tid >> 5;
    const int kw   = warp & 3;        // k-subtile (16 rows)
    const int nw   = warp >> 2;       // a-half (16 cols)
    const int r    = lane >> 2;
    const int q    = lane & 3;
    const int kblk = blockIdx.x * KT_CTA;

    const int k0g = kblk + kw * 16 + r;
    const int k1g = k0g + 8;
    const float t0 = angle[2 * k0g + 1];
    const float t1 = angle[2 * k1g + 1];

    // E1 epilogue constants
    const float s0 = angle[2 * k0g];
    const float s1 = angle[2 * k1g];
    float sttr[2], stti[2], advr[2], advi[2];
    float fc0r[2], fc0i[2], f1r[2], f1i[2], f8r[2], f8i[2];
    {
        const float ss[2] = {s0, s1};
        const int co0 = nw * 16 + 2 * q;
#pragma unroll
        for (int m = 0; m < 2; ++m) {
            sincosf(-128.0f * ss[m], &stti[m], &sttr[m]);
            sincosf(32.0f * ss[m], &advi[m], &advr[m]);
            sincosf(ss[m] * (float)co0, &fc0i[m], &fc0r[m]);
            sincosf(ss[m], &f1i[m], &f1r[m]);
            sincosf(8.0f * ss[m], &f8i[m], &f8r[m]);
        }
    }
    const float wk0 = w[k0g & (NVEC - 1)];
    const float wk1 = w[k1g & (NVEC - 1)];

    // loader: one STAGE = 512 16B-chunks, 2 per thread; parity swizzle
    auto issue_stage = [&](int st) {
        int cp_ = st >> 6, ach = (st >> 3) & 7, bq = st & 7;
        const char* src =
            (const char*)(gXh + (size_t)((cp_ * 16 + ach) * 8 + bq) * SLABH);
        uint32_t dst = XST + (uint32_t)(st & 3) * STAGEB;
#pragma unroll
        for (int j = 0; j < 2; ++j) {
            int ch  = tid + j * 256;
            int ci  = ch >> 8;
            int loc = ch & 255;
            int col = loc >> 3, blk = (loc >> 2) & 1, qq = loc & 3;
            uint32_t doff = (uint32_t)(ci * COILB + col * 128 +
                            ((blk * 64 + qq * 16) ^ ((col & 1) * 64)));
            cp16(dst + doff, src + (size_t)ci * (64 * SLABH * 2) + loc * 16);
        }
    };

    // prologue: pair 0 in flight
    issue_stage(0); issue_stage(1); CP_COMMIT();

    // ---- generate E2 fragment table (once per CTA; nw==0 warps) ----
    if (nw == 0) {
        float er_[2][2], ei_[2][2];
        sincosf(t0 * (float)(2 * q - 128), &ei_[0][0], &er_[0][0]);
        sincosf(t0 * (float)(2 * q - 120), &ei_[0][1], &er_[0][1]);
        sincosf(t1 * (float)(2 * q - 128), &ei_[1][0], &er_[1][0]);
        sincosf(t1 * (float)(2 * q - 120), &ei_[1][1], &er_[1][1]);
        float r1r[2], r1i[2], st16r[2], st16i[2];
        sincosf(t0, &r1i[0], &r1r[0]);
        sincosf(t1, &r1i[1], &r1r[1]);
        sincosf(16.0f * t0, &st16i[0], &st16r[0]);
        sincosf(16.0f * t1, &st16i[1], &st16r[1]);

        uint32_t ga = TBL + (uint32_t)kw * 16384 + (uint32_t)lane * 16;
#pragma unroll 4
        for (int bb2 = 0; bb2 < 16; ++bb2) {
            uint32_t Ar[4], Ai[4];
#pragma unroll
            for (int o = 0; o < 2; ++o)
#pragma unroll
                for (int m = 0; m < 2; ++m) {
                    float br = er_[m][o], bi = ei_[m][o];
                    float nr2 = br * r1r[m] - bi * r1i[m];
                    float ni2 = br * r1i[m] + bi * r1r[m];
                    int idx = o * 2 + m;
                    Ar[idx] = pack2(br, nr2);
                    Ai[idx] = pack2(bi, ni2);
                }
            sts128(ga, Ar);
            sts128(ga + 512, Ai);
            ga += 1024;
#pragma unroll
            for (int m = 0; m < 2; ++m)
#pragma unroll
                for (int o = 0; o < 2; ++o) {
                    float nr2 = er_[m][o] * st16r[m] - ei_[m][o] * st16i[m];
                    ei_[m][o] = fmaf(er_[m][o], st16i[m], ei_[m][o] * st16r[m]);
                    er_[m][o] = nr2;
                }
        }
    }

    float yr[2][2] = {}, yi[2][2] = {};
    float runr[2] = {sttr[0], sttr[1]}, runi[2] = {stti[0], stti[1]};

    const uint32_t TA0 = TBL + (uint32_t)kw * 16384 + (uint32_t)lane * 16;
    // per-thread B offsets with parity swizzle (col parity = r&1)
    const uint32_t swz  = (uint32_t)((r & 1) * 64);
    const uint32_t ob0  = (uint32_t)(q * 16) + swz;
    const uint32_t ob1  = (uint32_t)(q * 16) + (64u ^ swz);
    int st = 0;

#pragma unroll 1
    for (int cp = 0; cp < 4; ++cp) {
#pragma unroll 1
        for (int ach = 0; ach < 8; ++ach) {
            float P1[2][2][4] = {}, P2[2][2][4] = {}, P3[2][2][4] = {};

#pragma unroll 1
            for (int bqp = 0; bqp < 4; ++bqp) {       // pairs of bq stages
                CP_WAIT0();
                __syncthreads();
                if (st + 2 < NSTAGE) {
                    issue_stage(st + 2); issue_stage(st + 3); CP_COMMIT();
                }
#pragma unroll
                for (int half = 0; half < 2; ++half) {
                    const int s = st + half;
                    const uint32_t bb  = XST + (uint32_t)(s & 3) * STAGEB;
                    const uint32_t riB = bb + (uint32_t)(nw * 16 + r) * 128;
                    const uint32_t TA  = TA0 + (uint32_t)(s & 7) * 2048;
#pragma unroll
                    for (int blk = 0; blk < 2; ++blk) {
                        uint32_t Ar[4], Ai[4], As[4];
                        lds128(Ar[0], Ar[1], Ar[2], Ar[3], TA + blk * 1024);
                        lds128(Ai[0], Ai[1], Ai[2], Ai[3], TA + blk * 1024 + 512);
#pragma unroll
                        for (int j = 0; j < 4; ++j) As[j] = hadd2u(Ar[j], Ai[j]);
                        const uint32_t ob = blk ? ob1 : ob0;
#pragma unroll
                        for (int ci = 0; ci < 2; ++ci)
#pragma unroll
                            for (int nt = 0; nt < 2; ++nt) {
                                uint32_t rlo, rhi, ilo, ihi;
                                lds128(rlo, rhi, ilo, ihi,
                                       riB + ci * COILB + nt * 1024 + ob);
                                uint32_t slo = hadd2u(rlo, ilo);
                                uint32_t shi = hadd2u(rhi, ihi);
                                mma16(P1[ci][nt], Ar, rlo, rhi);
                                mma16(P2[ci][nt], Ai, ilo, ihi);
                                mma16(P3[ci][nt], As, slo, shi);
                            }
                    }
                }
                st += 2;
            }

            // ---- epilogue: y += e1 * T (3M combine) ----
#pragma unroll
            for (int m = 0; m < 2; ++m) {
                float b0r = runr[m] * fc0r[m] - runi[m] * fc0i[m];
                float b0i = runr[m] * fc0i[m] + runi[m] * fc0r[m];
#pragma unroll
                for (int nt = 0; nt < 2; ++nt) {
                    float cr_ = b0r, ci_ = b0i;
                    if (nt == 1) {
                        cr_ = b0r * f8r[m] - b0i * f8i[m];
                        ci_ = b0r * f8i[m] + b0i * f8r[m];
                    }
#pragma unroll
                    for (int j = 0; j < 2; ++j) {
                        float er2 = cr_, ei2 = ci_;
                        if (j == 1) {
                            er2 = cr_ * f1r[m] - ci_ * f1i[m];
                            ei2 = cr_ * f1i[m] + ci_ * f1r[m];
                        }
                        int e = m * 2 + j;
#pragma unroll
                        for (int ci2 = 0; ci2 < 2; ++ci2) {
                            float p1 = P1[ci2][nt][e], p2 = P2[ci2][nt][e];
                            float Tr = p1 - p2;
                            float Ti = P3[ci2][nt][e] - p1 - p2;
                            yr[ci2][m] = fmaf(er2, Tr, yr[ci2][m]);
                            yr[ci2][m] = fmaf(-ei2, Ti, yr[ci2][m]);
                            yi[ci2][m] = fmaf(er2, Ti, yi[ci2][m]);
                            yi[ci2][m] = fmaf(ei2, Tr, yi[ci2][m]);
                        }
                    }
                }
            }
#pragma unroll
            for (int m = 0; m < 2; ++m) {
                float nr2 = runr[m] * advr[m] - runi[m] * advi[m];
                runi[m] = fmaf(runr[m], advi[m], runi[m] * advr[m]);
                runr[m] = nr2;
            }
        } // ach

        // ---- writeout coil pair cp ----
#pragma unroll
        for (int ci = 0; ci < 2; ++ci)
#pragma unroll
            for (int m = 0; m < 2; ++m) {
                yr[ci][m] += __shfl_xor_sync(0xffffffffu, yr[ci][m], 1);
                yr[ci][m] += __shfl_xor_sync(0xffffffffu, yr[ci][m], 2);
                yi[ci][m] += __shfl_xor_sync(0xffffffffu, yi[ci][m], 1);
                yi[ci][m] += __shfl_xor_sync(0xffffffffu, yi[ci][m], 2);
            }
        if (nw == 1 && q == 0) {
            sred[0][kw * 16 + r]     = make_float2(yr[0][0], yi[0][0]);
            sred[0][kw * 16 + 8 + r] = make_float2(yr[0][1], yi[0][1]);
            sred[1][kw * 16 + r]     = make_float2(yr[1][0], yi[1][0]);
            sred[1][kw * 16 + 8 + r] = make_float2(yr[1][1], yi[1][1]);
        }
        __syncthreads();
        if (nw == 0 && q == 0) {
            int c0 = cp * 2;
#pragma unroll
            for (int ci = 0; ci < 2; ++ci) {
                float2 p0 = sred[ci][kw * 16 + r];
                float2 p1 = sred[ci][kw * 16 + 8 + r];
                size_t o0 = ((size_t)(c0 + ci) * KTOT + k0g) * 2;
                size_t o1 = ((size_t)(c0 + ci) * KTOT + k1g) * 2;
                out[o0 + 0] = (yr[ci][0] + p0.x) * wk0;
                out[o0 + 1] = (yi[ci][0] + p0.y) * wk0;
                out[o1 + 0] = (yr[ci][1] + p1.x) * wk1;
                out[o1 + 1] = (yi[ci][1] + p1.y) * wk1;
            }
        }
#pragma unroll
        for (int ci = 0; ci < 2; ++ci)
#pragma unroll
            for (int m = 0; m < 2; ++m) { yr[ci][m] = 0.f; yi[ci][m] = 0.f; }
#pragma unroll
        for (int m = 0; m < 2; ++m) { runr[m] = sttr[m]; runi[m] = stti[m]; }
    } // cp
}

// ------------------------- launch -------------------------
extern "C" void kernel_launch(void* const* d_in, const int* in_sizes, int n_in,
                              void* d_out, int out_size) {
    const float* input_r = (const float*)d_in[0];
    const float* C_r     = (const float*)d_in[1];
    const float* w       = (const float*)d_in[2];
    const float* angle   = (const float*)d_in[3];
    float* out = (float*)d_out;

    prep_X<<<(NCOIL * NN * NN + 255) / 256, 256>>>(input_r, C_r);

    cudaFuncSetAttribute(main_kernel,
                         cudaFuncAttributeMaxDynamicSharedMemorySize, SMEM_BYTES);
    main_kernel<<<NCTA, 256, SMEM_BYTES>>>(angle, w, out);
}